// round 9
// baseline (speedup 1.0000x reference)
#include <cuda_runtime.h>

#define B_  128
#define N_  4096
#define K_  100
#define P_  4096
#define T_  1024          // threads per block

// Device globals (no allocation in kernel_launch, per harness rules)
__device__ double g_loss[B_];
__device__ int    g_flag[B_];    // zero-init; block 0 resets after consuming

#define F_INF __int_as_float(0x7f800000)

// ---------------------------------------------------------------------------
// Single fused kernel. One block per row b, 1024 threads. grid=128 <= #SMs,
// so all blocks are co-resident (flag-based completion is deadlock-free).
//   Loads: critical t/a float4 first, then pointx, then tiny targeted
//          prefetch of the likely gather window of x/p.
//   Phase 1: sign-only scan of u = target/amp -> warp partials -> bar
//   Phase 1b+2 (warp 0 only): reduce -> shift (register) -> gather K=100
//            shifted X / dvals into shared -> bar
//   Phase 3: stable rank-sort (8 threads/element), packed {x,d,idx} -> bar
//   Phase 4: per point branchless binary search + 2-candidate NN
//            (exact jnp.argmin first-index tie-break)
//   Phase 5: variance (ddof=0, points 1..P-1); float accum, double combine
//   Phase 6: blocks 1..127 publish loss via fence+flag; block 0 polls,
//            reduces the 128 losses, writes mean, resets flags.
// ---------------------------------------------------------------------------
__global__ void __launch_bounds__(T_, 1)
k_fused(const float* __restrict__ preds,
        const float* __restrict__ target,
        const float* __restrict__ Xffp,
        const float* __restrict__ amp,
        const float* __restrict__ pointx,
        float* __restrict__ out)
{
    const int b   = blockIdx.x;
    const int tid = threadIdx.x;          // 1024
    const int w   = tid >> 5, l = tid & 31;

    const float* t = target + (size_t)b * N_;
    const float* a = amp    + (size_t)b * N_;
    const float* p = preds  + (size_t)b * N_;
    const float* x = Xffp   + (size_t)b * N_;

    // ---- Critical loads FIRST: they gate the whole phase chain ----
    const float4 tv4 = ((const float4*)t)[tid];
    const float4 av4 = ((const float4*)a)[tid];

    // pointx next (needed only in Phase 4)
    float px[4];
    #pragma unroll
    for (int j = 0; j < 4; j++) px[j] = pointx[tid + j * T_];

    // Targeted prefetch of the likely gather window (shift is a first-zero-
    // crossing index, almost always small): x/p[0..255] + the last line.
    // Pure hint — correctness does not depend on coverage.
    if (tid >= 32 && tid < 40)
        asm volatile("prefetch.global.L1 [%0];" :: "l"(x + (tid - 32) * 32));
    else if (tid >= 40 && tid < 48)
        asm volatile("prefetch.global.L1 [%0];" :: "l"(p + (tid - 40) * 32));
    else if (tid == 48)
        asm volatile("prefetch.global.L1 [%0];" :: "l"(x + N_ - 32));
    else if (tid == 49)
        asm volatile("prefetch.global.L1 [%0];" :: "l"(p + N_ - 32));

    // ---- Phase 1: min index with u>=0, max index with u<=0 (sign-only) ----
    int minGe = N_;
    int maxLe = -1;
    {
        const float tv[4] = {tv4.x, tv4.y, tv4.z, tv4.w};
        const float av[4] = {av4.x, av4.y, av4.z, av4.w};
        #pragma unroll
        for (int c = 3; c >= 0; c--) {       // descending: first match = min idx
            int  sgn = __float_as_int(tv[c]) ^ __float_as_int(av[c]);
            bool zer = (tv[c] == 0.0f);
            if (zer || sgn >= 0) minGe = tid * 4 + c;       // u >= 0
        }
        #pragma unroll
        for (int c = 0; c <= 3; c++) {       // ascending: last match = max idx
            int  sgn = __float_as_int(tv[c]) ^ __float_as_int(av[c]);
            bool zer = (tv[c] == 0.0f);
            if (zer || sgn < 0) maxLe = tid * 4 + c;        // u <= 0
        }
    }
    minGe = __reduce_min_sync(0xffffffffu, minGe);
    maxLe = __reduce_max_sync(0xffffffffu, maxLe);
    __shared__ int   sMin[32], sMax[32];
    __shared__ float sFL[4];                 // t0, a0, tN, aN from registers
    if (l == 0) { sMin[w] = minGe; sMax[w] = maxLe; }
    if (tid == 0)      { sFL[0] = tv4.x; sFL[1] = av4.x; }
    if (tid == T_ - 1) { sFL[2] = tv4.w; sFL[3] = av4.w; }   // t[4095], a[4095]
    __syncthreads();                                         // barrier 1

    // ---- Phase 1b + 2 (warp 0): reduce -> shift -> gather K=100 ----
    __shared__ float sX[K_], sD[K_];
    if (w == 0) {
        int mg = __reduce_min_sync(0xffffffffu, sMin[l]);    // same value, all lanes
        int ml = __reduce_max_sync(0xffffffffu, sMax[l]);
        int j_left  = (mg == N_) ? 0 : mg;                   // jnp.argmax all-False -> 0
        int m_right = (ml < 0)   ? 0 : (N_ - 1 - ml);
        // u < 0  <=>  sign(t)^sign(a) set and t != 0 (division-free)
        bool firstNeg = ((__float_as_int(sFL[0]) ^ __float_as_int(sFL[1])) < 0)
                        && (sFL[0] != 0.0f);
        bool lastNeg  = ((__float_as_int(sFL[2]) ^ __float_as_int(sFL[3])) < 0)
                        && (sFL[2] != 0.0f);
        const int shift = (lastNeg && firstNeg) ? -(j_left + 1) : m_right;
        #pragma unroll
        for (int q = 0; q < 4; q++) {
            int k = l + q * 32;
            if (k < K_) {
                int src = (k - shift) % N_;
                if (src < 0) src += N_;
                float av = a[src];                       // t/a rows are L1-hot
                sX[k] = x[src];                          // prefetched window
                sD[k] = t[src] / av - p[src] / av;       // u - u_uifft (as in ref)
            }
        }
    }
    __syncthreads();                                         // barrier 2

    // ---- Phase 3: stable rank-sort, 8 threads per element ----
    __shared__ float  sXs[K_];
    __shared__ float4 sPk[K_];                 // {x, d, orig idx (bits), 0}
    {
        const int k = tid >> 3, part = tid & 7;
        if (k < K_) {
            float v = sX[k];
            int r = 0;
            for (int j = part; j < K_; j += 8) {
                float u = sX[j];
                r += (u < v) || (u == v && j < k);
            }
            r += __shfl_down_sync(0xffffffffu, r, 4, 8);
            r += __shfl_down_sync(0xffffffffu, r, 2, 8);
            r += __shfl_down_sync(0xffffffffu, r, 1, 8);
            if (part == 0) {
                sXs[r] = v;
                sPk[r] = make_float4(v, sD[k], __int_as_float(k), 0.f);
            }
        }
    }
    __syncthreads();                                         // barrier 3

    // ---- Phase 4+5: binary-search NN + variance, 4 points/thread ----
    float s = 0.f, s2 = 0.f;
    #pragma unroll
    for (int j = 0; j < 4; j++) {
        const int   pi = tid + j * T_;
        const float pv = px[j];
        // branchless lower_bound: pos = #elements < pv
        int pos = 0;
        #pragma unroll
        for (int step = 64; step >= 1; step >>= 1)
            if (pos + step <= K_ && sXs[pos + step - 1] < pv) pos += step;
        // two candidates: pos-1 (strictly < pv) and pos (>= pv)
        float dL = F_INF, vL = 0.f; int iL = 0x7fffffff;
        if (pos > 0) {
            float4 c = sPk[pos - 1];
            dL = fabsf(pv - c.x); vL = c.y; iL = __float_as_int(c.z);
        }
        float dR = F_INF, vR = 0.f; int iR = 0x7fffffff;
        if (pos < K_) {
            float4 c = sPk[pos];
            dR = fabsf(pv - c.x); vR = c.y; iR = __float_as_int(c.z);
        }
        bool takeL = (dL < dR) || (dL == dR && iL < iR);   // first-index tie-break
        float dv = takeL ? vL : vR;
        if (pi >= 1) {                         // diff[:, 1:] excludes point 0
            s  += dv;
            s2  = fmaf(dv, dv, s2);
        }
    }
    #pragma unroll
    for (int o = 16; o > 0; o >>= 1) {
        s  += __shfl_down_sync(0xffffffffu, s,  o);
        s2 += __shfl_down_sync(0xffffffffu, s2, o);
    }
    __shared__ float rs[32], rs2[32];
    if (l == 0) { rs[w] = s; rs2[w] = s2; }
    __syncthreads();                                         // barrier 4
    if (w == 0) {
        double ds  = (double)rs [l];
        double ds2 = (double)rs2[l];
        #pragma unroll
        for (int o = 16; o > 0; o >>= 1) {
            ds  += __shfl_down_sync(0xffffffffu, ds,  o);
            ds2 += __shfl_down_sync(0xffffffffu, ds2, o);
        }
        if (l == 0) {
            const double M = (double)(P_ - 1);   // 4095, ddof=0
            double mean = ds / M;
            g_loss[b] = ds2 / M - mean * mean;
        }
    }

    // ---- Phase 6: flag-based completion (no atomics) ----
    if (b != 0) {
        if (w == 0 && l == 0) {
            __threadfence();                    // order g_loss[b] before flag
            *(volatile int*)&g_flag[b] = 1;
        }
        return;
    }
    // Block 0: poll the 127 flags (all blocks co-resident -> no deadlock).
    // The first __syncthreads_and also orders warp 0's g_loss[0] write for
    // the block-0 readers below.
    bool mydone;
    do {
        int f = 1;
        if (tid > 0 && tid < B_) f = *(volatile int*)&g_flag[tid];
        mydone = (f != 0);
    } while (!__syncthreads_and(mydone));
    __threadfence();                            // acquire: order loss reads

    double v = (tid < B_) ? g_loss[tid] : 0.0;
    #pragma unroll
    for (int o = 16; o > 0; o >>= 1) v += __shfl_down_sync(0xffffffffu, v, o);
    __shared__ double rr[4];
    if (w < 4 && l == 0) rr[w] = v;
    __syncthreads();
    if (tid == 0)
        out[0] = (float)((rr[0] + rr[1] + rr[2] + rr[3]) / (double)B_);
    if (tid > 0 && tid < B_)
        g_flag[tid] = 0;                        // reset for next graph replay
}

// ---------------------------------------------------------------------------
// Inputs (metadata order): preds, target, Xffp, dXffp_Amp, pointx
// Output: scalar float32
// ---------------------------------------------------------------------------
extern "C" void kernel_launch(void* const* d_in, const int* in_sizes, int n_in,
                              void* d_out, int out_size)
{
    const float* preds  = (const float*)d_in[0];
    const float* target = (const float*)d_in[1];
    const float* Xffp   = (const float*)d_in[2];
    const float* amp    = (const float*)d_in[3];
    const float* pointx = (const float*)d_in[4];

    k_fused<<<B_, T_>>>(preds, target, Xffp, amp, pointx, (float*)d_out);
}

// round 11
// speedup vs baseline: 1.1636x; 1.1636x over previous
#include <cuda_runtime.h>

#define B_  128
#define N_  4096
#define K_  100
#define P_  4096
#define T_  1024          // threads per block

// Device globals (no allocation in kernel_launch, per harness rules)
__device__ double g_loss[B_];
__device__ int    g_flag[B_];    // zero-init; block 0 resets after consuming

#define F_INF __int_as_float(0x7f800000)

// ---------------------------------------------------------------------------
// Single fused kernel. One block per row b, 1024 threads. grid=128 <= #SMs,
// so all blocks are co-resident (flag-based completion is deadlock-free).
//   Loads: critical t/a float4 FIRST (they gate the phase chain), then
//          pointx, then full-row L1 prefetch of x/p (hides Phase-2 gather).
//   Phase 1: sign-only scan of u = target/amp -> shift (no divisions;
//            first/last elements forwarded from registers via shared)
//   Phase 2: block-wide gather of K=100 shifted X / dvals into shared
//   Phase 3: stable rank-sort (8 threads/element), packed {x,d,idx} float4
//   Phase 4: per point branchless binary search + 2-candidate NN
//            (exact jnp.argmin first-index tie-break)
//   Phase 5: variance (ddof=0, points 1..P-1); float accum, double combine
//   Phase 6: blocks 1..127 publish loss via fence+flag; block 0 polls,
//            reduces the 128 losses, writes mean, resets flags.
// ---------------------------------------------------------------------------
__global__ void __launch_bounds__(T_, 1)
k_fused(const float* __restrict__ preds,
        const float* __restrict__ target,
        const float* __restrict__ Xffp,
        const float* __restrict__ amp,
        const float* __restrict__ pointx,
        float* __restrict__ out)
{
    const int b   = blockIdx.x;
    const int tid = threadIdx.x;          // 1024
    const int w   = tid >> 5, l = tid & 31;

    const float* t = target + (size_t)b * N_;
    const float* a = amp    + (size_t)b * N_;
    const float* p = preds  + (size_t)b * N_;
    const float* x = Xffp   + (size_t)b * N_;

    // ---- Critical loads FIRST: t/a gate the whole phase chain ----
    const float4 tv4 = ((const float4*)t)[tid];
    const float4 av4 = ((const float4*)a)[tid];

    // pointx next (needed only in Phase 4)
    float px[4];
    #pragma unroll
    for (int j = 0; j < 4; j++) px[j] = pointx[tid + j * T_];

    // Full-row L1 prefetch of x/p (hides Phase-2's scattered gather; proven
    // load-bearing in R8 vs R9). Issued last so it can't delay t/a.
    if (tid < 128)
        asm volatile("prefetch.global.L1 [%0];" :: "l"(x + tid * 32));
    else if (tid < 256)
        asm volatile("prefetch.global.L1 [%0];" :: "l"(p + (tid - 128) * 32));

    // ---- Phase 1: min index with u>=0, max index with u<=0 (sign-only) ----
    int minGe = N_;
    int maxLe = -1;
    {
        const float tv[4] = {tv4.x, tv4.y, tv4.z, tv4.w};
        const float av[4] = {av4.x, av4.y, av4.z, av4.w};
        #pragma unroll
        for (int c = 3; c >= 0; c--) {       // descending: first match = min idx
            int  sgn = __float_as_int(tv[c]) ^ __float_as_int(av[c]);
            bool zer = (tv[c] == 0.0f);
            if (zer || sgn >= 0) minGe = tid * 4 + c;       // u >= 0
        }
        #pragma unroll
        for (int c = 0; c <= 3; c++) {       // ascending: last match = max idx
            int  sgn = __float_as_int(tv[c]) ^ __float_as_int(av[c]);
            bool zer = (tv[c] == 0.0f);
            if (zer || sgn < 0) maxLe = tid * 4 + c;        // u <= 0
        }
    }
    minGe = __reduce_min_sync(0xffffffffu, minGe);
    maxLe = __reduce_max_sync(0xffffffffu, maxLe);
    __shared__ int   sMin[32], sMax[32];
    __shared__ float sFL[4];                 // t0, a0, tN, aN from registers
    __shared__ int   sShift;
    if (l == 0) { sMin[w] = minGe; sMax[w] = maxLe; }
    if (tid == 0)      { sFL[0] = tv4.x; sFL[1] = av4.x; }
    if (tid == T_ - 1) { sFL[2] = tv4.w; sFL[3] = av4.w; }   // t[4095], a[4095]
    __syncthreads();                                         // barrier 1
    if (w == 0) {
        int mg = __reduce_min_sync(0xffffffffu, sMin[l]);
        int ml = __reduce_max_sync(0xffffffffu, sMax[l]);
        if (l == 0) {
            int j_left  = (mg == N_) ? 0 : mg;             // jnp.argmax all-False -> 0
            int m_right = (ml < 0)   ? 0 : (N_ - 1 - ml);
            // u < 0  <=>  sign(t)^sign(a) set and t != 0 (division-free)
            bool firstNeg = ((__float_as_int(sFL[0]) ^ __float_as_int(sFL[1])) < 0)
                            && (sFL[0] != 0.0f);
            bool lastNeg  = ((__float_as_int(sFL[2]) ^ __float_as_int(sFL[3])) < 0)
                            && (sFL[2] != 0.0f);
            sShift = (lastNeg && firstNeg) ? -(j_left + 1) : m_right;
        }
    }
    __syncthreads();                                         // barrier 2

    // ---- Phase 2: block-wide gather of K=100 shifted values (L1-hot) ----
    __shared__ float sX[K_], sD[K_];
    if (tid < K_) {
        int src = (tid - sShift) % N_;
        if (src < 0) src += N_;
        float av = a[src];
        sX[tid] = x[src];
        sD[tid] = t[src] / av - p[src] / av;   // u - u_uifft (two divisions, as in ref)
    }
    __syncthreads();                                         // barrier 3

    // ---- Phase 3: stable rank-sort, 8 threads per element ----
    __shared__ float  sXs[K_];
    __shared__ float4 sPk[K_];                 // {x, d, orig idx (bits), 0}
    {
        const int k = tid >> 3, part = tid & 7;
        if (k < K_) {
            float v = sX[k];
            int r = 0;
            for (int j = part; j < K_; j += 8) {
                float u = sX[j];
                r += (u < v) || (u == v && j < k);
            }
            r += __shfl_down_sync(0xffffffffu, r, 4, 8);
            r += __shfl_down_sync(0xffffffffu, r, 2, 8);
            r += __shfl_down_sync(0xffffffffu, r, 1, 8);
            if (part == 0) {
                sXs[r] = v;
                sPk[r] = make_float4(v, sD[k], __int_as_float(k), 0.f);
            }
        }
    }
    __syncthreads();                                         // barrier 4

    // ---- Phase 4+5: binary-search NN + variance, 4 points/thread ----
    float s = 0.f, s2 = 0.f;
    #pragma unroll
    for (int j = 0; j < 4; j++) {
        const int   pi = tid + j * T_;
        const float pv = px[j];
        // branchless lower_bound: pos = #elements < pv
        int pos = 0;
        #pragma unroll
        for (int step = 64; step >= 1; step >>= 1)
            if (pos + step <= K_ && sXs[pos + step - 1] < pv) pos += step;
        // two candidates: pos-1 (strictly < pv) and pos (>= pv)
        float dL = F_INF, vL = 0.f; int iL = 0x7fffffff;
        if (pos > 0) {
            float4 c = sPk[pos - 1];
            dL = fabsf(pv - c.x); vL = c.y; iL = __float_as_int(c.z);
        }
        float dR = F_INF, vR = 0.f; int iR = 0x7fffffff;
        if (pos < K_) {
            float4 c = sPk[pos];
            dR = fabsf(pv - c.x); vR = c.y; iR = __float_as_int(c.z);
        }
        bool takeL = (dL < dR) || (dL == dR && iL < iR);   // first-index tie-break
        float dv = takeL ? vL : vR;
        if (pi >= 1) {                         // diff[:, 1:] excludes point 0
            s  += dv;
            s2  = fmaf(dv, dv, s2);
        }
    }
    #pragma unroll
    for (int o = 16; o > 0; o >>= 1) {
        s  += __shfl_down_sync(0xffffffffu, s,  o);
        s2 += __shfl_down_sync(0xffffffffu, s2, o);
    }
    __shared__ float rs[32], rs2[32];
    if (l == 0) { rs[w] = s; rs2[w] = s2; }
    __syncthreads();                                         // barrier 5
    if (w == 0) {
        double ds  = (double)rs [l];
        double ds2 = (double)rs2[l];
        #pragma unroll
        for (int o = 16; o > 0; o >>= 1) {
            ds  += __shfl_down_sync(0xffffffffu, ds,  o);
            ds2 += __shfl_down_sync(0xffffffffu, ds2, o);
        }
        if (l == 0) {
            const double M = (double)(P_ - 1);   // 4095, ddof=0
            double mean = ds / M;
            g_loss[b] = ds2 / M - mean * mean;
        }
    }

    // ---- Phase 6: flag-based completion (no atomics) ----
    if (b != 0) {
        if (w == 0 && l == 0) {
            __threadfence();                    // order g_loss[b] before flag
            *(volatile int*)&g_flag[b] = 1;
        }
        return;
    }
    // Block 0: poll the 127 flags (all blocks co-resident -> no deadlock).
    // The first __syncthreads_and also orders warp 0's g_loss[0] write for
    // the block-0 readers below.
    bool mydone;
    do {
        int f = 1;
        if (tid > 0 && tid < B_) f = *(volatile int*)&g_flag[tid];
        mydone = (f != 0);
    } while (!__syncthreads_and(mydone));
    __threadfence();                            // acquire: order loss reads

    double v = (tid < B_) ? g_loss[tid] : 0.0;
    #pragma unroll
    for (int o = 16; o > 0; o >>= 1) v += __shfl_down_sync(0xffffffffu, v, o);
    __shared__ double rr[4];
    if (w < 4 && l == 0) rr[w] = v;
    __syncthreads();
    if (tid == 0)
        out[0] = (float)((rr[0] + rr[1] + rr[2] + rr[3]) / (double)B_);
    if (tid > 0 && tid < B_)
        g_flag[tid] = 0;                        // reset for next graph replay
}

// ---------------------------------------------------------------------------
// Inputs (metadata order): preds, target, Xffp, dXffp_Amp, pointx
// Output: scalar float32
// ---------------------------------------------------------------------------
extern "C" void kernel_launch(void* const* d_in, const int* in_sizes, int n_in,
                              void* d_out, int out_size)
{
    const float* preds  = (const float*)d_in[0];
    const float* target = (const float*)d_in[1];
    const float* Xffp   = (const float*)d_in[2];
    const float* amp    = (const float*)d_in[3];
    const float* pointx = (const float*)d_in[4];

    k_fused<<<B_, T_>>>(preds, target, Xffp, amp, pointx, (float*)d_out);
}

// round 12
// speedup vs baseline: 1.3617x; 1.1702x over previous
#include <cuda_runtime.h>

#define B_  128
#define N_  4096
#define K_  100
#define P_  4096
#define T_  1024          // threads per block

// Device global (no allocation in kernel_launch, per harness rules).
// g_pub[b] = {loss_b, flag}; 16B-aligned; flag reset to 0 by block 0 each run.
__device__ double2 g_pub[B_];

#define F_INF __int_as_float(0x7f800000)

// ---------------------------------------------------------------------------
// Single fused kernel. One block per row b, 1024 threads. grid=128 <= #SMs,
// so all blocks are co-resident (poll-based completion is deadlock-free).
//   Loads: critical t/a float4 FIRST, then pointx, then full-row L1 prefetch
//          of x/p (hides Phase-2 gather; proven load-bearing R8 vs R9).
//   Phase 1: sign-only scan of u = target/amp -> 32 warp partials -> bar1;
//            warps 0-3 each redundantly reduce partials -> shift (no second
//            barrier, no serial warp-0 stage)
//   Phase 2: gather of K=100 shifted X / dvals into shared -> bar2
//   Phase 3: stable rank-sort (8 threads/element), packed {x,d,idx} -> bar3
//   Phase 4: per point branchless binary search + 2-candidate NN
//            (exact jnp.argmin first-index tie-break)
//   Phase 5: variance (ddof=0, points 1..P-1); float accum, double combine
//            -> bar4 -> warp 0 computes loss_b
//   Phase 6: every block publishes {loss,1} with ONE st.global.v2.f64 (flag
//            rides in the same 16B transaction -> no fence). Block 0's warp 0
//            polls all 128 entries with ld.volatile.global.v2.f64; on
//            completion the losses are already in registers -> warp reduce ->
//            out; flags reset for the next graph replay.
// ---------------------------------------------------------------------------
__global__ void __launch_bounds__(T_, 1)
k_fused(const float* __restrict__ preds,
        const float* __restrict__ target,
        const float* __restrict__ Xffp,
        const float* __restrict__ amp,
        const float* __restrict__ pointx,
        float* __restrict__ out)
{
    const int b   = blockIdx.x;
    const int tid = threadIdx.x;          // 1024
    const int w   = tid >> 5, l = tid & 31;

    const float* t = target + (size_t)b * N_;
    const float* a = amp    + (size_t)b * N_;
    const float* p = preds  + (size_t)b * N_;
    const float* x = Xffp   + (size_t)b * N_;

    // ---- Critical loads FIRST: t/a gate the whole phase chain ----
    const float4 tv4 = ((const float4*)t)[tid];
    const float4 av4 = ((const float4*)a)[tid];

    // pointx next (needed only in Phase 4)
    float px[4];
    #pragma unroll
    for (int j = 0; j < 4; j++) px[j] = pointx[tid + j * T_];

    // Full-row L1 prefetch of x/p, issued last so it can't delay t/a.
    if (tid < 128)
        asm volatile("prefetch.global.L1 [%0];" :: "l"(x + tid * 32));
    else if (tid < 256)
        asm volatile("prefetch.global.L1 [%0];" :: "l"(p + (tid - 128) * 32));

    // ---- Phase 1: min index with u>=0, max index with u<=0 (sign-only) ----
    int minGe = N_;
    int maxLe = -1;
    {
        const float tv[4] = {tv4.x, tv4.y, tv4.z, tv4.w};
        const float av[4] = {av4.x, av4.y, av4.z, av4.w};
        #pragma unroll
        for (int c = 3; c >= 0; c--) {       // descending: first match = min idx
            int  sgn = __float_as_int(tv[c]) ^ __float_as_int(av[c]);
            bool zer = (tv[c] == 0.0f);
            if (zer || sgn >= 0) minGe = tid * 4 + c;       // u >= 0
        }
        #pragma unroll
        for (int c = 0; c <= 3; c++) {       // ascending: last match = max idx
            int  sgn = __float_as_int(tv[c]) ^ __float_as_int(av[c]);
            bool zer = (tv[c] == 0.0f);
            if (zer || sgn < 0) maxLe = tid * 4 + c;        // u <= 0
        }
    }
    minGe = __reduce_min_sync(0xffffffffu, minGe);
    maxLe = __reduce_max_sync(0xffffffffu, maxLe);
    __shared__ int   sMin[32], sMax[32];
    __shared__ float sFL[4];                 // t0, a0, tN, aN from registers
    if (l == 0) { sMin[w] = minGe; sMax[w] = maxLe; }
    if (tid == 0)      { sFL[0] = tv4.x; sFL[1] = av4.x; }
    if (tid == T_ - 1) { sFL[2] = tv4.w; sFL[3] = av4.w; }   // t[4095], a[4095]
    __syncthreads();                                         // barrier 1

    // ---- Phase 2: warps 0-3 each derive shift, 100 threads gather ----
    __shared__ float sX[K_], sD[K_];
    if (tid < 128) {                          // full warps 0-3 only
        int mg = __reduce_min_sync(0xffffffffu, sMin[l]);    // same in all 4 warps
        int ml = __reduce_max_sync(0xffffffffu, sMax[l]);
        int j_left  = (mg == N_) ? 0 : mg;                   // jnp.argmax all-False -> 0
        int m_right = (ml < 0)   ? 0 : (N_ - 1 - ml);
        // u < 0  <=>  sign(t)^sign(a) set and t != 0 (division-free)
        bool firstNeg = ((__float_as_int(sFL[0]) ^ __float_as_int(sFL[1])) < 0)
                        && (sFL[0] != 0.0f);
        bool lastNeg  = ((__float_as_int(sFL[2]) ^ __float_as_int(sFL[3])) < 0)
                        && (sFL[2] != 0.0f);
        const int shift = (lastNeg && firstNeg) ? -(j_left + 1) : m_right;
        if (tid < K_) {
            int src = (tid - shift) % N_;
            if (src < 0) src += N_;
            sX[tid] = x[src];                                 // prefetched, L1-hot
            sD[tid] = (t[src] - p[src]) / a[src];             // == t/a - p/a to ~1ulp
        }
    }
    __syncthreads();                                         // barrier 2

    // ---- Phase 3: stable rank-sort, 8 threads per element ----
    __shared__ float  sXs[K_];
    __shared__ float4 sPk[K_];                 // {x, d, orig idx (bits), 0}
    {
        const int k = tid >> 3, part = tid & 7;
        if (k < K_) {
            float v = sX[k];
            int r = 0;
            for (int j = part; j < K_; j += 8) {
                float u = sX[j];
                r += (u < v) || (u == v && j < k);
            }
            r += __shfl_down_sync(0xffffffffu, r, 4, 8);
            r += __shfl_down_sync(0xffffffffu, r, 2, 8);
            r += __shfl_down_sync(0xffffffffu, r, 1, 8);
            if (part == 0) {
                sXs[r] = v;
                sPk[r] = make_float4(v, sD[k], __int_as_float(k), 0.f);
            }
        }
    }
    __syncthreads();                                         // barrier 3

    // ---- Phase 4+5: binary-search NN + variance, 4 points/thread ----
    float s = 0.f, s2 = 0.f;
    #pragma unroll
    for (int j = 0; j < 4; j++) {
        const int   pi = tid + j * T_;
        const float pv = px[j];
        // branchless lower_bound: pos = #elements < pv
        int pos = 0;
        #pragma unroll
        for (int step = 64; step >= 1; step >>= 1)
            if (pos + step <= K_ && sXs[pos + step - 1] < pv) pos += step;
        // two candidates: pos-1 (strictly < pv) and pos (>= pv)
        float dL = F_INF, vL = 0.f; int iL = 0x7fffffff;
        if (pos > 0) {
            float4 c = sPk[pos - 1];
            dL = fabsf(pv - c.x); vL = c.y; iL = __float_as_int(c.z);
        }
        float dR = F_INF, vR = 0.f; int iR = 0x7fffffff;
        if (pos < K_) {
            float4 c = sPk[pos];
            dR = fabsf(pv - c.x); vR = c.y; iR = __float_as_int(c.z);
        }
        bool takeL = (dL < dR) || (dL == dR && iL < iR);   // first-index tie-break
        float dv = takeL ? vL : vR;
        if (pi >= 1) {                         // diff[:, 1:] excludes point 0
            s  += dv;
            s2  = fmaf(dv, dv, s2);
        }
    }
    #pragma unroll
    for (int o = 16; o > 0; o >>= 1) {
        s  += __shfl_down_sync(0xffffffffu, s,  o);
        s2 += __shfl_down_sync(0xffffffffu, s2, o);
    }
    __shared__ float rs[32], rs2[32];
    if (l == 0) { rs[w] = s; rs2[w] = s2; }
    __syncthreads();                                         // barrier 4 (last)

    if (w != 0) return;                       // warps 1-31 are done

    // ---- warp 0: finish loss, publish, (block 0) poll + finalize ----
    double ds  = (double)rs [l];
    double ds2 = (double)rs2[l];
    #pragma unroll
    for (int o = 16; o > 0; o >>= 1) {
        ds  += __shfl_down_sync(0xffffffffu, ds,  o);
        ds2 += __shfl_down_sync(0xffffffffu, ds2, o);
    }
    if (l == 0) {
        const double M = (double)(P_ - 1);    // 4095, ddof=0
        double mean = ds / M;
        double loss = ds2 / M - mean * mean;
        // Publish loss+flag in ONE 16B transaction (no fence needed).
        asm volatile("st.global.v2.f64 [%0], {%1, %2};"
                     :: "l"(&g_pub[b]), "d"(loss), "d"(1.0) : "memory");
    }
    if (b != 0) return;

    // Block 0, warp 0: poll all 128 {loss, flag} entries (4 rows per lane).
    double lx0, lx1, lx2, lx3;
    bool done;
    do {
        double f0, f1, f2, f3;
        asm volatile("ld.volatile.global.v2.f64 {%0,%1}, [%2];"
                     : "=d"(lx0), "=d"(f0) : "l"(&g_pub[l      ]));
        asm volatile("ld.volatile.global.v2.f64 {%0,%1}, [%2];"
                     : "=d"(lx1), "=d"(f1) : "l"(&g_pub[l +  32]));
        asm volatile("ld.volatile.global.v2.f64 {%0,%1}, [%2];"
                     : "=d"(lx2), "=d"(f2) : "l"(&g_pub[l +  64]));
        asm volatile("ld.volatile.global.v2.f64 {%0,%1}, [%2];"
                     : "=d"(lx3), "=d"(f3) : "l"(&g_pub[l +  96]));
        done = (f0 != 0.0) && (f1 != 0.0) && (f2 != 0.0) && (f3 != 0.0);
    } while (!__all_sync(0xffffffffu, done));

    double sum = (lx0 + lx1) + (lx2 + lx3);   // losses already in registers
    #pragma unroll
    for (int o = 16; o > 0; o >>= 1)
        sum += __shfl_down_sync(0xffffffffu, sum, o);
    if (l == 0)
        out[0] = (float)(sum / (double)B_);

    // Reset flags for the next graph replay (stream order protects replays).
    g_pub[l      ].y = 0.0;
    g_pub[l +  32].y = 0.0;
    g_pub[l +  64].y = 0.0;
    g_pub[l +  96].y = 0.0;
}

// ---------------------------------------------------------------------------
// Inputs (metadata order): preds, target, Xffp, dXffp_Amp, pointx
// Output: scalar float32
// ---------------------------------------------------------------------------
extern "C" void kernel_launch(void* const* d_in, const int* in_sizes, int n_in,
                              void* d_out, int out_size)
{
    const float* preds  = (const float*)d_in[0];
    const float* target = (const float*)d_in[1];
    const float* Xffp   = (const float*)d_in[2];
    const float* amp    = (const float*)d_in[3];
    const float* pointx = (const float*)d_in[4];

    k_fused<<<B_, T_>>>(preds, target, Xffp, amp, pointx, (float*)d_out);
}

// round 13
// speedup vs baseline: 1.3956x; 1.0249x over previous
#include <cuda_runtime.h>

#define B_  128
#define N_  4096
#define K_  100
#define P_  4096
#define T_  1024          // threads per block

// Device global (no allocation in kernel_launch, per harness rules).
// g_pub[b] = {loss_b, flag}; 16B-aligned; flag reset to 0 by block 0 each run.
__device__ double2 g_pub[B_];

#define F_INF __int_as_float(0x7f800000)

// ---------------------------------------------------------------------------
// Single fused kernel. One block per row b, 1024 threads. grid=128 <= #SMs,
// so all blocks are co-resident (poll-based completion is deadlock-free).
//   Loads: critical t/a float4 FIRST, then pointx, then full-row L1 prefetch
//          of x/p (hides Phase-2 gather; proven load-bearing R8 vs R9).
//   Phase 1: sign-only scan of u = target/amp -> 32 warp partials -> bar1;
//            warps 0-3 each redundantly reduce partials -> shift (no second
//            barrier, no serial warp-0 stage)
//   Phase 2: gather of K=100 shifted X / dvals into shared -> bar2
//   Phase 3: stable rank-sort (8 threads/element), packed {x,d,idx} -> bar3
//   Phase 4: per point branchless binary search + 2-candidate NN
//            (exact jnp.argmin first-index tie-break)
//   Phase 5: variance (ddof=0, points 1..P-1); float accum, double combine
//            -> bar4 -> warp 0 computes loss_b
//   Phase 6: every block publishes {loss,1} with ONE st.global.v2.f64 (flag
//            rides in the same 16B transaction -> no fence). Block 0's warp 0
//            polls all 128 entries with ld.volatile.global.v2.f64; on
//            completion the losses are already in registers -> warp reduce ->
//            out; flags reset for the next graph replay.
// ---------------------------------------------------------------------------
__global__ void __launch_bounds__(T_, 1)
k_fused(const float* __restrict__ preds,
        const float* __restrict__ target,
        const float* __restrict__ Xffp,
        const float* __restrict__ amp,
        const float* __restrict__ pointx,
        float* __restrict__ out)
{
    const int b   = blockIdx.x;
    const int tid = threadIdx.x;          // 1024
    const int w   = tid >> 5, l = tid & 31;

    const float* t = target + (size_t)b * N_;
    const float* a = amp    + (size_t)b * N_;
    const float* p = preds  + (size_t)b * N_;
    const float* x = Xffp   + (size_t)b * N_;

    // ---- Critical loads FIRST: t/a gate the whole phase chain ----
    const float4 tv4 = ((const float4*)t)[tid];
    const float4 av4 = ((const float4*)a)[tid];

    // pointx next (needed only in Phase 4)
    float px[4];
    #pragma unroll
    for (int j = 0; j < 4; j++) px[j] = pointx[tid + j * T_];

    // Full-row L1 prefetch of x/p, issued last so it can't delay t/a.
    if (tid < 128)
        asm volatile("prefetch.global.L1 [%0];" :: "l"(x + tid * 32));
    else if (tid < 256)
        asm volatile("prefetch.global.L1 [%0];" :: "l"(p + (tid - 128) * 32));

    // ---- Phase 1: min index with u>=0, max index with u<=0 (sign-only) ----
    int minGe = N_;
    int maxLe = -1;
    {
        const float tv[4] = {tv4.x, tv4.y, tv4.z, tv4.w};
        const float av[4] = {av4.x, av4.y, av4.z, av4.w};
        #pragma unroll
        for (int c = 3; c >= 0; c--) {       // descending: first match = min idx
            int  sgn = __float_as_int(tv[c]) ^ __float_as_int(av[c]);
            bool zer = (tv[c] == 0.0f);
            if (zer || sgn >= 0) minGe = tid * 4 + c;       // u >= 0
        }
        #pragma unroll
        for (int c = 0; c <= 3; c++) {       // ascending: last match = max idx
            int  sgn = __float_as_int(tv[c]) ^ __float_as_int(av[c]);
            bool zer = (tv[c] == 0.0f);
            if (zer || sgn < 0) maxLe = tid * 4 + c;        // u <= 0
        }
    }
    minGe = __reduce_min_sync(0xffffffffu, minGe);
    maxLe = __reduce_max_sync(0xffffffffu, maxLe);
    __shared__ int   sMin[32], sMax[32];
    __shared__ float sFL[4];                 // t0, a0, tN, aN from registers
    if (l == 0) { sMin[w] = minGe; sMax[w] = maxLe; }
    if (tid == 0)      { sFL[0] = tv4.x; sFL[1] = av4.x; }
    if (tid == T_ - 1) { sFL[2] = tv4.w; sFL[3] = av4.w; }   // t[4095], a[4095]
    __syncthreads();                                         // barrier 1

    // ---- Phase 2: warps 0-3 each derive shift, 100 threads gather ----
    __shared__ float sX[K_], sD[K_];
    if (tid < 128) {                          // full warps 0-3 only
        int mg = __reduce_min_sync(0xffffffffu, sMin[l]);    // same in all 4 warps
        int ml = __reduce_max_sync(0xffffffffu, sMax[l]);
        int j_left  = (mg == N_) ? 0 : mg;                   // jnp.argmax all-False -> 0
        int m_right = (ml < 0)   ? 0 : (N_ - 1 - ml);
        // u < 0  <=>  sign(t)^sign(a) set and t != 0 (division-free)
        bool firstNeg = ((__float_as_int(sFL[0]) ^ __float_as_int(sFL[1])) < 0)
                        && (sFL[0] != 0.0f);
        bool lastNeg  = ((__float_as_int(sFL[2]) ^ __float_as_int(sFL[3])) < 0)
                        && (sFL[2] != 0.0f);
        const int shift = (lastNeg && firstNeg) ? -(j_left + 1) : m_right;
        if (tid < K_) {
            int src = (tid - shift) % N_;
            if (src < 0) src += N_;
            sX[tid] = x[src];                                 // prefetched, L1-hot
            sD[tid] = (t[src] - p[src]) / a[src];             // == t/a - p/a to ~1ulp
        }
    }
    __syncthreads();                                         // barrier 2

    // ---- Phase 3: stable rank-sort, 8 threads per element ----
    __shared__ float  sXs[K_];
    __shared__ float4 sPk[K_];                 // {x, d, orig idx (bits), 0}
    {
        const int k = tid >> 3, part = tid & 7;
        if (k < K_) {
            float v = sX[k];
            int r = 0;
            for (int j = part; j < K_; j += 8) {
                float u = sX[j];
                r += (u < v) || (u == v && j < k);
            }
            r += __shfl_down_sync(0xffffffffu, r, 4, 8);
            r += __shfl_down_sync(0xffffffffu, r, 2, 8);
            r += __shfl_down_sync(0xffffffffu, r, 1, 8);
            if (part == 0) {
                sXs[r] = v;
                sPk[r] = make_float4(v, sD[k], __int_as_float(k), 0.f);
            }
        }
    }
    __syncthreads();                                         // barrier 3

    // ---- Phase 4+5: binary-search NN + variance, 4 points/thread ----
    float s = 0.f, s2 = 0.f;
    #pragma unroll
    for (int j = 0; j < 4; j++) {
        const int   pi = tid + j * T_;
        const float pv = px[j];
        // branchless lower_bound: pos = #elements < pv
        int pos = 0;
        #pragma unroll
        for (int step = 64; step >= 1; step >>= 1)
            if (pos + step <= K_ && sXs[pos + step - 1] < pv) pos += step;
        // two candidates: pos-1 (strictly < pv) and pos (>= pv)
        float dL = F_INF, vL = 0.f; int iL = 0x7fffffff;
        if (pos > 0) {
            float4 c = sPk[pos - 1];
            dL = fabsf(pv - c.x); vL = c.y; iL = __float_as_int(c.z);
        }
        float dR = F_INF, vR = 0.f; int iR = 0x7fffffff;
        if (pos < K_) {
            float4 c = sPk[pos];
            dR = fabsf(pv - c.x); vR = c.y; iR = __float_as_int(c.z);
        }
        bool takeL = (dL < dR) || (dL == dR && iL < iR);   // first-index tie-break
        float dv = takeL ? vL : vR;
        if (pi >= 1) {                         // diff[:, 1:] excludes point 0
            s  += dv;
            s2  = fmaf(dv, dv, s2);
        }
    }
    #pragma unroll
    for (int o = 16; o > 0; o >>= 1) {
        s  += __shfl_down_sync(0xffffffffu, s,  o);
        s2 += __shfl_down_sync(0xffffffffu, s2, o);
    }
    __shared__ float rs[32], rs2[32];
    if (l == 0) { rs[w] = s; rs2[w] = s2; }
    __syncthreads();                                         // barrier 4 (last)

    if (w != 0) return;                       // warps 1-31 are done

    // ---- warp 0: finish loss, publish, (block 0) poll + finalize ----
    double ds  = (double)rs [l];
    double ds2 = (double)rs2[l];
    #pragma unroll
    for (int o = 16; o > 0; o >>= 1) {
        ds  += __shfl_down_sync(0xffffffffu, ds,  o);
        ds2 += __shfl_down_sync(0xffffffffu, ds2, o);
    }
    if (l == 0) {
        const double M = (double)(P_ - 1);    // 4095, ddof=0
        double mean = ds / M;
        double loss = ds2 / M - mean * mean;
        // Publish loss+flag in ONE 16B transaction (no fence needed).
        asm volatile("st.global.v2.f64 [%0], {%1, %2};"
                     :: "l"(&g_pub[b]), "d"(loss), "d"(1.0) : "memory");
    }
    if (b != 0) return;

    // Block 0, warp 0: poll all 128 {loss, flag} entries (4 rows per lane).
    double lx0, lx1, lx2, lx3;
    bool done;
    do {
        double f0, f1, f2, f3;
        asm volatile("ld.volatile.global.v2.f64 {%0,%1}, [%2];"
                     : "=d"(lx0), "=d"(f0) : "l"(&g_pub[l      ]));
        asm volatile("ld.volatile.global.v2.f64 {%0,%1}, [%2];"
                     : "=d"(lx1), "=d"(f1) : "l"(&g_pub[l +  32]));
        asm volatile("ld.volatile.global.v2.f64 {%0,%1}, [%2];"
                     : "=d"(lx2), "=d"(f2) : "l"(&g_pub[l +  64]));
        asm volatile("ld.volatile.global.v2.f64 {%0,%1}, [%2];"
                     : "=d"(lx3), "=d"(f3) : "l"(&g_pub[l +  96]));
        done = (f0 != 0.0) && (f1 != 0.0) && (f2 != 0.0) && (f3 != 0.0);
    } while (!__all_sync(0xffffffffu, done));

    double sum = (lx0 + lx1) + (lx2 + lx3);   // losses already in registers
    #pragma unroll
    for (int o = 16; o > 0; o >>= 1)
        sum += __shfl_down_sync(0xffffffffu, sum, o);
    if (l == 0)
        out[0] = (float)(sum / (double)B_);

    // Reset flags for the next graph replay (stream order protects replays).
    g_pub[l      ].y = 0.0;
    g_pub[l +  32].y = 0.0;
    g_pub[l +  64].y = 0.0;
    g_pub[l +  96].y = 0.0;
}

// ---------------------------------------------------------------------------
// Inputs (metadata order): preds, target, Xffp, dXffp_Amp, pointx
// Output: scalar float32
// ---------------------------------------------------------------------------
extern "C" void kernel_launch(void* const* d_in, const int* in_sizes, int n_in,
                              void* d_out, int out_size)
{
    const float* preds  = (const float*)d_in[0];
    const float* target = (const float*)d_in[1];
    const float* Xffp   = (const float*)d_in[2];
    const float* amp    = (const float*)d_in[3];
    const float* pointx = (const float*)d_in[4];

    k_fused<<<B_, T_>>>(preds, target, Xffp, amp, pointx, (float*)d_out);
}